// round 11
// baseline (speedup 1.0000x reference)
#include <cuda_runtime.h>
#include <math.h>

#define N_NODES 10000
#define N_EDGES 100000

#define INV_SQRT3    0.57735026918962576f
#define NORM_MSG     0.036084391824351614f   // 1/sqrt(768)
#define NORM_MSG_V3  (0.036084391824351614f * 0.57735026918962576f)
#define NORM_UPD_S   0.011811391307201575f   // 1/sqrt(7168)
#define NORM_UPD_V   0.013975424859373686f   // 1/sqrt(5120)
#define NORM_LIN64   0.125f                  // 1/sqrt(64)
#define NORM_LIN32   0.17677669529663687f    // 1/sqrt(32)

#define ZSTRIDE 4096
// per-node factored message tensor product (norms folded in):
// [0,768) Zss[v<8][w<96], [768,3072) Zvv[(v*3+m)<24][w<96],
// [3072,3328) Zsv[v<8][w<32], [3328,4096) Zvs[v<8][(w*3+m)<96]
__device__ float g_z[(size_t)N_NODES * ZSTRIDE];
__device__ float g_agg[N_NODES * 192];   // [96 scalars | 32x3 vectors] per node
__device__ float g_upd[N_NODES * 192];   // raw partial sums: us[96] | uv[u*3+m]

__global__ void zero_kernel() {
    int i = blockIdx.x * blockDim.x + threadIdx.x;
    if (i < N_NODES * 192) { g_agg[i] = 0.f; g_upd[i] = 0.f; }
}

// ============================================================================
// Z PRECOMPUTE: 32 nodes/block, 256 threads.  (unchanged)
// ============================================================================
__global__ void __launch_bounds__(256) precompute_z(
    const float* __restrict__ nf,
    const float* __restrict__ Wss, const float* __restrict__ Wvv,
    const float* __restrict__ Wsv, const float* __restrict__ Wvs)
{
    __shared__ float s_xs[32 * 64];
    __shared__ float s_xv[32 * 96];
    const int t = threadIdx.x;
    const int n0 = blockIdx.x * 32;

    for (int i = t; i < 32 * 160; i += 256) {
        int n = i / 160, c = i - n * 160;
        int gn = n0 + n;
        float v = (gn < N_NODES) ? nf[(size_t)gn * 160 + c] : 0.f;
        if (c < 64) s_xs[n * 64 + c] = v; else s_xv[n * 96 + (c - 64)] = v;
    }
    __syncthreads();

    const int ng = t >> 6;
    const int c0 = t & 63;

    for (int c = c0; c < 768; c += 64) {
        float acc[8] = {0,0,0,0,0,0,0,0};
        #pragma unroll 8
        for (int u = 0; u < 64; u++) {
            float b = Wss[u * 768 + c];
            #pragma unroll
            for (int j = 0; j < 8; j++)
                acc[j] = fmaf(s_xs[(ng * 8 + j) * 64 + u], b, acc[j]);
        }
        #pragma unroll
        for (int j = 0; j < 8; j++) {
            int gn = n0 + ng * 8 + j;
            if (gn < N_NODES) g_z[(size_t)gn * ZSTRIDE + c] = acc[j] * NORM_MSG;
        }
    }
    for (int c = c0; c < 2304; c += 64) {
        int v = c / 288, rem = c - v * 288;
        int m = rem / 96, w = rem - m * 96;
        float acc[8] = {0,0,0,0,0,0,0,0};
        #pragma unroll 8
        for (int u = 0; u < 32; u++) {
            float b = Wvv[u * 768 + v * 96 + w];
            #pragma unroll
            for (int j = 0; j < 8; j++)
                acc[j] = fmaf(s_xv[(ng * 8 + j) * 96 + u * 3 + m], b, acc[j]);
        }
        #pragma unroll
        for (int j = 0; j < 8; j++) {
            int gn = n0 + ng * 8 + j;
            if (gn < N_NODES) g_z[(size_t)gn * ZSTRIDE + 768 + c] = acc[j] * NORM_MSG_V3;
        }
    }
    for (int c = c0; c < 256; c += 64) {
        float acc[8] = {0,0,0,0,0,0,0,0};
        #pragma unroll 8
        for (int u = 0; u < 64; u++) {
            float b = Wsv[u * 256 + c];
            #pragma unroll
            for (int j = 0; j < 8; j++)
                acc[j] = fmaf(s_xs[(ng * 8 + j) * 64 + u], b, acc[j]);
        }
        #pragma unroll
        for (int j = 0; j < 8; j++) {
            int gn = n0 + ng * 8 + j;
            if (gn < N_NODES) g_z[(size_t)gn * ZSTRIDE + 3072 + c] = acc[j] * NORM_MSG;
        }
    }
    for (int c = c0; c < 768; c += 64) {
        int v = c / 96, rem = c - v * 96;
        int w = rem / 3, m = rem - w * 3;
        float acc[8] = {0,0,0,0,0,0,0,0};
        #pragma unroll 8
        for (int u = 0; u < 32; u++) {
            float b = Wvs[u * 256 + v * 32 + w];
            #pragma unroll
            for (int j = 0; j < 8; j++)
                acc[j] = fmaf(s_xv[(ng * 8 + j) * 96 + u * 3 + m], b, acc[j]);
        }
        #pragma unroll
        for (int j = 0; j < 8; j++) {
            int gn = n0 + ng * 8 + j;
            if (gn < N_NODES) g_z[(size_t)gn * ZSTRIDE + 3328 + c] = acc[j] * NORM_MSG;
        }
    }
}

// ============================================================================
// EDGE KERNEL: warp-per-edge, 8 edges / 256-thread block.  (R8 version)
// ============================================================================
#define EB 8
__global__ void __launch_bounds__(256) edge_kernel(
    const float* __restrict__ ea,
    const float* __restrict__ WLs, const float* __restrict__ WLv,
    const int* __restrict__ eidx)
{
    __shared__ float s_WLs[64 * 96];
    __shared__ float s_WLv[32 * 32];
    __shared__ float s_y [EB * 32];
    __shared__ float s_ms[EB * 96];
    __shared__ float s_mv[EB * 96];

    const int t = threadIdx.x;
    for (int i = t; i < 6144; i += 256) s_WLs[i] = WLs[i];
    for (int i = t; i < 1024; i += 256) s_WLv[i] = WLv[i];

    const int es = t >> 5, l = t & 31;
    const int e = blockIdx.x * EB + es;
    s_y[es * 32 + l] = ea[(size_t)e * 32 + l];
    __syncthreads();

    const int row = eidx[e];
    const int col = eidx[N_EDGES + e];
    const float* Z  = g_z + (size_t)col * ZSTRIDE;
    const float* ye = s_y + es * 32;
    float* ms = s_ms + es * 96;
    float* mv = s_mv + es * 96;

    float a0 = 0.f, a1 = 0.f, a2 = 0.f;
    #pragma unroll 8
    for (int q = 0; q < 32; q++) {
        float y = ye[q];
        const float* zr = Z + q * 96;
        a0 = fmaf(y, zr[l],      a0);
        a1 = fmaf(y, zr[l + 32], a1);
        a2 = fmaf(y, zr[l + 64], a2);
    }
    ms[l]      = a0 / (1.f + expf(-a0));
    ms[32 + l] = a1 / (1.f + expf(-a1));
    ms[64 + l] = 1.f / (1.f + expf(-a2));
    __syncwarp();

    const float* Zsv = Z + 3072;
    const float* Zvs = Z + 3328;
    #pragma unroll
    for (int cc = 0; cc < 3; cc++) {
        int c = l + cc * 32;
        int w = c / 3, m = c - w * 3;
        float acc = 0.f;
        #pragma unroll
        for (int v = 0; v < 8; v++) {
            acc = fmaf(ye[v],             Zvs[v * 96 + c], acc);
            acc = fmaf(ye[8 + v * 3 + m], Zsv[v * 32 + w], acc);
        }
        mv[c] = acc * ms[64 + w];
    }
    __syncwarp();

    const size_t base = (size_t)row * 192;
    #pragma unroll
    for (int cc = 0; cc < 3; cc++) {
        int w = l + cc * 32;
        float acc = 0.f;
        #pragma unroll 8
        for (int u = 0; u < 64; u++)
            acc = fmaf(ms[u], s_WLs[u * 96 + w], acc);
        atomicAdd(&g_agg[base + w], acc * NORM_LIN64);
    }
    #pragma unroll
    for (int cc = 0; cc < 3; cc++) {
        int c = l + cc * 32;
        int w = c / 3, m = c - w * 3;
        float acc = 0.f;
        #pragma unroll
        for (int u = 0; u < 32; u++)
            acc = fmaf(mv[u * 3 + m], s_WLv[u * 32 + w], acc);
        atomicAdd(&g_agg[base + 96 + c], acc * NORM_LIN32);
    }
}

// ============================================================================
// NODE KERNEL v5: 64 nodes/block, 128 threads, 48 outputs/thread, 2-way
// K-split (grid = 2*157). Kc=8, ~102KB smem -> 2 blocks/SM.
// smem (floats): xsT[64u][64n]@0(4096)  xvT[3][32][64]@4096(6144)
//   asT[96][64]@10240(6144)  avT[3][32][64]@16384(6144)
//   sCh 2x1792@22528 (st1: A 512 | B 768; st2: A 1536 | B 256)
// ============================================================================
#define NODE_SMEM_BYTES (26112 * 4)

__device__ __forceinline__ float4 build1_4(const float* xsT, const float* asT,
                                           const float* xvT, const float* avT,
                                           int k, int n4) {
    float4 r;
    if (k < 6144) {
        int u = k / 96, v = k - u * 96;
        float4 x = *(const float4*)&xsT[u * 64 + n4];
        float4 a = *(const float4*)&asT[v * 64 + n4];
        r.x = x.x * a.x; r.y = x.y * a.y; r.z = x.z * a.z; r.w = x.w * a.w;
    } else {
        int k2 = k - 6144, u = k2 >> 5, v = k2 & 31;
        float sx = 0.f, sy = 0.f, sz = 0.f, sw = 0.f;
        #pragma unroll
        for (int m = 0; m < 3; m++) {
            float4 x = *(const float4*)&xvT[m * 2048 + u * 64 + n4];
            float4 a = *(const float4*)&avT[m * 2048 + v * 64 + n4];
            sx = fmaf(x.x, a.x, sx); sy = fmaf(x.y, a.y, sy);
            sz = fmaf(x.z, a.z, sz); sw = fmaf(x.w, a.w, sw);
        }
        r.x = INV_SQRT3 * sx; r.y = INV_SQRT3 * sy;
        r.z = INV_SQRT3 * sz; r.w = INV_SQRT3 * sw;
    }
    return r;
}

// 12 consecutive rows r (r = m*64+n over 192 rows)
__device__ __forceinline__ void build2_12(const float* xsT, const float* asT,
                                          const float* xvT, const float* avT,
                                          int k, int r0, float* o) {
    if (k < 2048) {
        int u = k >> 5, v = k & 31;
        #pragma unroll
        for (int j = 0; j < 12; j++) {
            int r = r0 + j, m = r >> 6, n = r & 63;
            o[j] = xsT[u * 64 + n] * avT[m * 2048 + v * 64 + n];
        }
    } else {
        int k2 = k - 2048, u = k2 / 96, v = k2 - u * 96;
        #pragma unroll
        for (int j = 0; j < 12; j++) {
            int r = r0 + j, m = r >> 6, n = r & 63;
            o[j] = xvT[m * 2048 + u * 64 + n] * asT[v * 64 + n];
        }
    }
}

__global__ void __launch_bounds__(128) node_kernel(
    const float* __restrict__ nf,
    const float* __restrict__ Wss, const float* __restrict__ Wvv,
    const float* __restrict__ Wsv, const float* __restrict__ Wvs)
{
    extern __shared__ float sm[];
    float* s_xsT = sm;
    float* s_xvT = sm + 4096;
    float* s_asT = sm + 10240;
    float* s_avT = sm + 16384;
    float* sCh   = sm + 22528;   // 2 x 1792

    const int t    = threadIdx.x;
    const int tile = blockIdx.x >> 1;
    const int half = blockIdx.x & 1;
    const int n0   = tile * 64;

    for (int i = t; i < 64 * 160; i += 128) {
        int n = i / 160, c = i - n * 160;
        int gn = n0 + n;
        float v = (gn < N_NODES) ? nf[(size_t)gn * 160 + c] : 0.f;
        if (c < 64) s_xsT[c * 64 + n] = v;
        else { int c2 = c - 64, u = c2 / 3, m = c2 - u * 3;
               s_xvT[m * 2048 + u * 64 + n] = v; }
    }
    for (int i = t; i < 64 * 192; i += 128) {
        int n = i / 192, c = i - n * 192;
        int gn = n0 + n;
        float v = (gn < N_NODES) ? g_agg[(size_t)gn * 192 + c] : 0.f;
        if (c < 96) s_asT[c * 64 + n] = v;
        else { int c2 = c - 96, w = c2 / 3, m = c2 - w * 3;
               s_avT[m * 2048 + w * 64 + n] = v; }
    }
    __syncthreads();

    // staging maps: 16 threads per k-row, Kc=8
    const int kb   = t >> 4;          // k-row 0..7
    const int n4b  = (t & 15) * 4;    // stage1 A: 4 nodes
    const int wB6  = (t & 15) * 6;    // stage1 B: 6 w
    const int r12  = (t & 15) * 12;   // stage2 A: 12 rows
    const int w2B  = (t & 15) * 2;    // stage2 B: 2 w

    // ---------------- stage 1: us partial, 448 chunks of 8 ----------------
    {
        const int k_off = half * 3584;
        const int n8 = (t & 7) * 8;      // compute: 8 nodes
        const int w6 = (t >> 3) * 6;     // compute: 6 w
        float acc[48];
        #pragma unroll
        for (int i = 0; i < 48; i++) acc[i] = 0.f;

        {   // prologue
            int kw = k_off + kb;
            float4 a0 = build1_4(s_xsT, s_asT, s_xvT, s_avT, kw, n4b);
            *(float4*)&sCh[kb * 64 + n4b] = a0;
            const float* src = (kw < 6144) ? Wss + (size_t)kw * 96 + wB6
                                           : Wvv + (size_t)(kw - 6144) * 96 + wB6;
            *(float2*)&sCh[512 + kb * 96 + wB6    ] = *(const float2*)(src);
            *(float2*)&sCh[512 + kb * 96 + wB6 + 2] = *(const float2*)(src + 2);
            *(float2*)&sCh[512 + kb * 96 + wB6 + 4] = *(const float2*)(src + 4);
        }
        __syncthreads();

        int cur = 0;
        for (int c = 0; c < 448; c++) {
            float4 an;
            float2 bn0, bn1, bn2;
            const bool pre = (c + 1 < 448);
            if (pre) {
                int kw = k_off + (c + 1) * 8 + kb;
                const float* src = (kw < 6144) ? Wss + (size_t)kw * 96 + wB6
                                               : Wvv + (size_t)(kw - 6144) * 96 + wB6;
                bn0 = *(const float2*)(src);
                bn1 = *(const float2*)(src + 2);
                bn2 = *(const float2*)(src + 4);
                an = build1_4(s_xsT, s_asT, s_xvT, s_avT, kw, n4b);
            }
            const float* A = sCh + cur * 1792;
            const float* B = A + 512;
            #pragma unroll
            for (int kk = 0; kk < 8; kk++) {
                float4 a0 = *(const float4*)&A[kk * 64 + n8];
                float4 a1 = *(const float4*)&A[kk * 64 + n8 + 4];
                float2 b0 = *(const float2*)&B[kk * 96 + w6];
                float2 b1 = *(const float2*)&B[kk * 96 + w6 + 2];
                float2 b2 = *(const float2*)&B[kk * 96 + w6 + 4];
                float av[8] = {a0.x, a0.y, a0.z, a0.w, a1.x, a1.y, a1.z, a1.w};
                float bv[6] = {b0.x, b0.y, b1.x, b1.y, b2.x, b2.y};
                #pragma unroll
                for (int i = 0; i < 8; i++)
                    #pragma unroll
                    for (int j = 0; j < 6; j++)
                        acc[i * 6 + j] = fmaf(av[i], bv[j], acc[i * 6 + j]);
            }
            if (pre) {
                float* An = sCh + (cur ^ 1) * 1792;
                float* Bn = An + 512;
                *(float4*)&An[kb * 64 + n4b] = an;
                *(float2*)&Bn[kb * 96 + wB6    ] = bn0;
                *(float2*)&Bn[kb * 96 + wB6 + 2] = bn1;
                *(float2*)&Bn[kb * 96 + wB6 + 4] = bn2;
            }
            __syncthreads();
            cur ^= 1;
        }
        #pragma unroll
        for (int i = 0; i < 8; i++) {
            int gn = n0 + n8 + i;
            if (gn < N_NODES) {
                #pragma unroll
                for (int j = 0; j < 6; j++)
                    atomicAdd(&g_upd[(size_t)gn * 192 + w6 + j], acc[i * 6 + j]);
            }
        }
    }
    __syncthreads();

    // ---------------- stage 2: uv partial, 320 chunks of 8 ----------------
    {
        const int k_off = half * 2560;
        const int r6 = (t >> 2) * 6;     // compute: 6 rows (of 192)
        const int w8 = (t & 3) * 8;      // compute: 8 w (of 32)
        float acc[48];
        #pragma unroll
        for (int i = 0; i < 48; i++) acc[i] = 0.f;

        {   // prologue
            int kw = k_off + kb;
            float o[12];
            build2_12(s_xsT, s_asT, s_xvT, s_avT, kw, r12, o);
            #pragma unroll
            for (int j = 0; j < 12; j += 4)
                *(float4*)&sCh[kb * 192 + r12 + j] = *(float4*)&o[j];
            const float* src = (kw < 2048) ? Wsv + (size_t)kw * 32 + w2B
                                           : Wvs + (size_t)(kw - 2048) * 32 + w2B;
            *(float2*)&sCh[1536 + kb * 32 + w2B] = *(const float2*)src;
        }
        __syncthreads();

        int cur = 0;
        for (int c = 0; c < 320; c++) {
            float on[12];
            float2 bn;
            const bool pre = (c + 1 < 320);
            if (pre) {
                int kw = k_off + (c + 1) * 8 + kb;
                const float* src = (kw < 2048) ? Wsv + (size_t)kw * 32 + w2B
                                               : Wvs + (size_t)(kw - 2048) * 32 + w2B;
                bn = *(const float2*)src;
                build2_12(s_xsT, s_asT, s_xvT, s_avT, kw, r12, on);
            }
            const float* A = sCh + cur * 1792;
            const float* B = A + 1536;
            #pragma unroll
            for (int kk = 0; kk < 8; kk++) {
                float2 a01 = *(const float2*)&A[kk * 192 + r6];
                float2 a23 = *(const float2*)&A[kk * 192 + r6 + 2];
                float2 a45 = *(const float2*)&A[kk * 192 + r6 + 4];
                float4 b0  = *(const float4*)&B[kk * 32 + w8];
                float4 b1  = *(const float4*)&B[kk * 32 + w8 + 4];
                float av[6] = {a01.x, a01.y, a23.x, a23.y, a45.x, a45.y};
                float bv[8] = {b0.x, b0.y, b0.z, b0.w, b1.x, b1.y, b1.z, b1.w};
                #pragma unroll
                for (int i = 0; i < 6; i++)
                    #pragma unroll
                    for (int j = 0; j < 8; j++)
                        acc[i * 8 + j] = fmaf(av[i], bv[j], acc[i * 8 + j]);
            }
            if (pre) {
                float* An = sCh + (cur ^ 1) * 1792;
                float* Bn = An + 1536;
                #pragma unroll
                for (int j = 0; j < 12; j += 4)
                    *(float4*)&An[kb * 192 + r12 + j] = *(float4*)&on[j];
                *(float2*)&Bn[kb * 32 + w2B] = bn;
            }
            __syncthreads();
            cur ^= 1;
        }
        #pragma unroll
        for (int i = 0; i < 6; i++) {
            int r = r6 + i, m = r >> 6, n = r & 63;
            int gn = n0 + n;
            if (gn < N_NODES) {
                #pragma unroll
                for (int j = 0; j < 8; j++)
                    atomicAdd(&g_upd[(size_t)gn * 192 + 96 + (w8 + j) * 3 + m],
                              acc[i * 8 + j]);
            }
        }
    }
}

// ============================================================================
// EPILOGUE: norm + gate + linear + residual.  (unchanged)
// ============================================================================
__global__ void __launch_bounds__(128) epilogue_kernel(
    const float* __restrict__ nf,
    const float* __restrict__ WLs, const float* __restrict__ WLv,
    float* __restrict__ out)
{
    __shared__ float s_WLs[4096];
    __shared__ float s_WLv[1024];
    __shared__ float s_us[3072];
    __shared__ float s_uv[3072];

    const int t  = threadIdx.x;
    const int n0 = blockIdx.x * 32;

    for (int i = t; i < 4096; i += 128) s_WLs[i] = WLs[i];
    for (int i = t; i < 1024; i += 128) s_WLv[i] = WLv[i];
    for (int i = t; i < 3072; i += 128) {
        int n = i / 96, c = i - n * 96;
        int gn = n0 + n;
        float us = 0.f, uv = 0.f;
        if (gn < N_NODES) {
            us = g_upd[(size_t)gn * 192 + c];
            uv = g_upd[(size_t)gn * 192 + 96 + c];
        }
        s_us[i] = us; s_uv[i] = uv;
    }
    __syncthreads();

    for (int i = t; i < 2048; i += 128) {
        int n = i >> 6, u = i & 63;
        float x = s_us[n * 96 + u] * NORM_UPD_S;
        s_us[n * 96 + u] = x / (1.f + expf(-x));
    }
    for (int i = t; i < 1024; i += 128) {
        int n = i >> 5, w = i & 31;
        float x = s_us[n * 96 + 64 + w] * NORM_UPD_S;
        s_us[n * 96 + 64 + w] = 1.f / (1.f + expf(-x));
    }
    __syncthreads();
    for (int i = t; i < 3072; i += 128) {
        int n = i / 96, c = i - n * 96;
        int u = c / 3;
        s_uv[i] = s_uv[i] * NORM_UPD_V * s_us[n * 96 + 64 + u];
    }
    __syncthreads();

    for (int i = t; i < 2048; i += 128) {
        int n = i >> 6, w = i & 63;
        int gn = n0 + n;
        if (gn < N_NODES) {
            float s = 0.f;
            #pragma unroll 8
            for (int u = 0; u < 64; u++)
                s = fmaf(s_us[n * 96 + u], s_WLs[u * 64 + w], s);
            out[(size_t)gn * 160 + w] = nf[(size_t)gn * 160 + w] + s * NORM_LIN64;
        }
    }
    for (int i = t; i < 3072; i += 128) {
        int n = i / 96, c = i - n * 96;
        int w = c / 3, m = c - w * 3;
        int gn = n0 + n;
        if (gn < N_NODES) {
            float s = 0.f;
            #pragma unroll
            for (int u = 0; u < 32; u++)
                s = fmaf(s_uv[n * 96 + u * 3 + m], s_WLv[u * 32 + w], s);
            out[(size_t)gn * 160 + 64 + c] = nf[(size_t)gn * 160 + 64 + c] + s * NORM_LIN32;
        }
    }
}

extern "C" void kernel_launch(void* const* d_in, const int* in_sizes, int n_in,
                              void* d_out, int out_size) {
    const float* nf   = (const float*)d_in[0];
    const float* ea   = (const float*)d_in[1];
    const float* Wmss = (const float*)d_in[2];
    const float* Wmvv = (const float*)d_in[3];
    const float* Wmsv = (const float*)d_in[4];
    const float* Wmvs = (const float*)d_in[5];
    const float* WLms = (const float*)d_in[6];
    const float* WLmv = (const float*)d_in[7];
    const float* Wuss = (const float*)d_in[8];
    const float* Wuvv = (const float*)d_in[9];
    const float* Wusv = (const float*)d_in[10];
    const float* Wuvs = (const float*)d_in[11];
    const float* WLus = (const float*)d_in[12];
    const float* WLuv = (const float*)d_in[13];
    const int*   eidx = (const int*)d_in[14];
    float* out = (float*)d_out;

    cudaFuncSetAttribute(node_kernel, cudaFuncAttributeMaxDynamicSharedMemorySize,
                         NODE_SMEM_BYTES);
    cudaFuncSetAttribute(node_kernel, cudaFuncAttributePreferredSharedMemoryCarveout,
                         100);

    zero_kernel<<<(N_NODES * 192 + 255) / 256, 256>>>();
    precompute_z<<<(N_NODES + 31) / 32, 256>>>(nf, Wmss, Wmvv, Wmsv, Wmvs);
    edge_kernel<<<N_EDGES / EB, 256>>>(ea, WLms, WLmv, eidx);
    node_kernel<<<2 * ((N_NODES + 63) / 64), 128, NODE_SMEM_BYTES>>>(
        nf, Wuss, Wuvv, Wusv, Wuvs);
    epilogue_kernel<<<(N_NODES + 31) / 32, 128>>>(nf, WLus, WLuv, out);
}

// round 12
// speedup vs baseline: 1.5390x; 1.5390x over previous
#include <cuda_runtime.h>
#include <math.h>

#define N_NODES 10000
#define N_EDGES 100000

#define INV_SQRT3    0.57735026918962576f
#define NORM_MSG     0.036084391824351614f   // 1/sqrt(768)
#define NORM_MSG_V3  (0.036084391824351614f * 0.57735026918962576f)
#define NORM_UPD_S   0.011811391307201575f   // 1/sqrt(7168)
#define NORM_UPD_V   0.013975424859373686f   // 1/sqrt(5120)
#define NORM_LIN64   0.125f                  // 1/sqrt(64)
#define NORM_LIN32   0.17677669529663687f    // 1/sqrt(32)

#define ZSTRIDE 4096
// per-node factored message tensor product (norms folded in):
// [0,768) Zss[v<8][w<96], [768,3072) Zvv[(v*3+m)<24][w<96],
// [3072,3328) Zsv[v<8][w<32], [3328,4096) Zvs[v<8][(w*3+m)<96]
__device__ float g_z[(size_t)N_NODES * ZSTRIDE];
__device__ float g_agg[N_NODES * 192];   // [96 scalars | 32x3 vectors] per node
__device__ float g_upd[N_NODES * 192];   // raw partial sums: us[96] | uv[u*3+m]

__global__ void zero_kernel() {
    int i = blockIdx.x * blockDim.x + threadIdx.x;
    if (i < N_NODES * 192) { g_agg[i] = 0.f; g_upd[i] = 0.f; }
}

// ============================================================================
// Z PRECOMPUTE: 32 nodes/block, 256 threads.  (unchanged)
// ============================================================================
__global__ void __launch_bounds__(256) precompute_z(
    const float* __restrict__ nf,
    const float* __restrict__ Wss, const float* __restrict__ Wvv,
    const float* __restrict__ Wsv, const float* __restrict__ Wvs)
{
    __shared__ float s_xs[32 * 64];
    __shared__ float s_xv[32 * 96];
    const int t = threadIdx.x;
    const int n0 = blockIdx.x * 32;

    for (int i = t; i < 32 * 160; i += 256) {
        int n = i / 160, c = i - n * 160;
        int gn = n0 + n;
        float v = (gn < N_NODES) ? nf[(size_t)gn * 160 + c] : 0.f;
        if (c < 64) s_xs[n * 64 + c] = v; else s_xv[n * 96 + (c - 64)] = v;
    }
    __syncthreads();

    const int ng = t >> 6;
    const int c0 = t & 63;

    for (int c = c0; c < 768; c += 64) {
        float acc[8] = {0,0,0,0,0,0,0,0};
        #pragma unroll 8
        for (int u = 0; u < 64; u++) {
            float b = Wss[u * 768 + c];
            #pragma unroll
            for (int j = 0; j < 8; j++)
                acc[j] = fmaf(s_xs[(ng * 8 + j) * 64 + u], b, acc[j]);
        }
        #pragma unroll
        for (int j = 0; j < 8; j++) {
            int gn = n0 + ng * 8 + j;
            if (gn < N_NODES) g_z[(size_t)gn * ZSTRIDE + c] = acc[j] * NORM_MSG;
        }
    }
    for (int c = c0; c < 2304; c += 64) {
        int v = c / 288, rem = c - v * 288;
        int m = rem / 96, w = rem - m * 96;
        float acc[8] = {0,0,0,0,0,0,0,0};
        #pragma unroll 8
        for (int u = 0; u < 32; u++) {
            float b = Wvv[u * 768 + v * 96 + w];
            #pragma unroll
            for (int j = 0; j < 8; j++)
                acc[j] = fmaf(s_xv[(ng * 8 + j) * 96 + u * 3 + m], b, acc[j]);
        }
        #pragma unroll
        for (int j = 0; j < 8; j++) {
            int gn = n0 + ng * 8 + j;
            if (gn < N_NODES) g_z[(size_t)gn * ZSTRIDE + 768 + c] = acc[j] * NORM_MSG_V3;
        }
    }
    for (int c = c0; c < 256; c += 64) {
        float acc[8] = {0,0,0,0,0,0,0,0};
        #pragma unroll 8
        for (int u = 0; u < 64; u++) {
            float b = Wsv[u * 256 + c];
            #pragma unroll
            for (int j = 0; j < 8; j++)
                acc[j] = fmaf(s_xs[(ng * 8 + j) * 64 + u], b, acc[j]);
        }
        #pragma unroll
        for (int j = 0; j < 8; j++) {
            int gn = n0 + ng * 8 + j;
            if (gn < N_NODES) g_z[(size_t)gn * ZSTRIDE + 3072 + c] = acc[j] * NORM_MSG;
        }
    }
    for (int c = c0; c < 768; c += 64) {
        int v = c / 96, rem = c - v * 96;
        int w = rem / 3, m = rem - w * 3;
        float acc[8] = {0,0,0,0,0,0,0,0};
        #pragma unroll 8
        for (int u = 0; u < 32; u++) {
            float b = Wvs[u * 256 + v * 32 + w];
            #pragma unroll
            for (int j = 0; j < 8; j++)
                acc[j] = fmaf(s_xv[(ng * 8 + j) * 96 + u * 3 + m], b, acc[j]);
        }
        #pragma unroll
        for (int j = 0; j < 8; j++) {
            int gn = n0 + ng * 8 + j;
            if (gn < N_NODES) g_z[(size_t)gn * ZSTRIDE + 3328 + c] = acc[j] * NORM_MSG;
        }
    }
}

// ============================================================================
// EDGE KERNEL: warp-per-edge, 8 edges / 256-thread block.  (R8 version)
// ============================================================================
#define EB 8
__global__ void __launch_bounds__(256) edge_kernel(
    const float* __restrict__ ea,
    const float* __restrict__ WLs, const float* __restrict__ WLv,
    const int* __restrict__ eidx)
{
    __shared__ float s_WLs[64 * 96];
    __shared__ float s_WLv[32 * 32];
    __shared__ float s_y [EB * 32];
    __shared__ float s_ms[EB * 96];
    __shared__ float s_mv[EB * 96];

    const int t = threadIdx.x;
    for (int i = t; i < 6144; i += 256) s_WLs[i] = WLs[i];
    for (int i = t; i < 1024; i += 256) s_WLv[i] = WLv[i];

    const int es = t >> 5, l = t & 31;
    const int e = blockIdx.x * EB + es;
    s_y[es * 32 + l] = ea[(size_t)e * 32 + l];
    __syncthreads();

    const int row = eidx[e];
    const int col = eidx[N_EDGES + e];
    const float* Z  = g_z + (size_t)col * ZSTRIDE;
    const float* ye = s_y + es * 32;
    float* ms = s_ms + es * 96;
    float* mv = s_mv + es * 96;

    float a0 = 0.f, a1 = 0.f, a2 = 0.f;
    #pragma unroll 8
    for (int q = 0; q < 32; q++) {
        float y = ye[q];
        const float* zr = Z + q * 96;
        a0 = fmaf(y, zr[l],      a0);
        a1 = fmaf(y, zr[l + 32], a1);
        a2 = fmaf(y, zr[l + 64], a2);
    }
    ms[l]      = a0 / (1.f + expf(-a0));
    ms[32 + l] = a1 / (1.f + expf(-a1));
    ms[64 + l] = 1.f / (1.f + expf(-a2));
    __syncwarp();

    const float* Zsv = Z + 3072;
    const float* Zvs = Z + 3328;
    #pragma unroll
    for (int cc = 0; cc < 3; cc++) {
        int c = l + cc * 32;
        int w = c / 3, m = c - w * 3;
        float acc = 0.f;
        #pragma unroll
        for (int v = 0; v < 8; v++) {
            acc = fmaf(ye[v],             Zvs[v * 96 + c], acc);
            acc = fmaf(ye[8 + v * 3 + m], Zsv[v * 32 + w], acc);
        }
        mv[c] = acc * ms[64 + w];
    }
    __syncwarp();

    const size_t base = (size_t)row * 192;
    #pragma unroll
    for (int cc = 0; cc < 3; cc++) {
        int w = l + cc * 32;
        float acc = 0.f;
        #pragma unroll 8
        for (int u = 0; u < 64; u++)
            acc = fmaf(ms[u], s_WLs[u * 96 + w], acc);
        atomicAdd(&g_agg[base + w], acc * NORM_LIN64);
    }
    #pragma unroll
    for (int cc = 0; cc < 3; cc++) {
        int c = l + cc * 32;
        int w = c / 3, m = c - w * 3;
        float acc = 0.f;
        #pragma unroll
        for (int u = 0; u < 32; u++)
            acc = fmaf(mv[u * 3 + m], s_WLv[u * 32 + w], acc);
        atomicAdd(&g_agg[base + 96 + c], acc * NORM_LIN32);
    }
}

// ============================================================================
// NODE KERNEL v6 = R8 kernel with 8-way K-split (wave-quantization fix).
// grid = 8 * 313 (tile = bx>>3, kslice = bx&7); block ~110us -> fine waves.
// 128 threads, 32 nodes/tile, Kc=8, 53KB smem -> 4 blocks/SM.
// smem (floats): xsT[64][32]@0  xvT[3][32][32]@2048  asT[96][32]@5120
//   avT[3][32][32]@8192  sCh 2x1024@11264
// ============================================================================
#define KSPLIT 8
#define NODE_SMEM_BYTES (13312 * 4)

__device__ __forceinline__ float2 build1_2(const float* xsT, const float* asT,
                                           const float* xvT, const float* avT,
                                           int k, int n2) {
    float2 r;
    if (k < 6144) {
        int u = k / 96, v = k - u * 96;
        float2 x = *(const float2*)&xsT[u * 32 + n2];
        float2 a = *(const float2*)&asT[v * 32 + n2];
        r.x = x.x * a.x; r.y = x.y * a.y;
    } else {
        int k2 = k - 6144, u = k2 >> 5, v = k2 & 31;
        float sx = 0.f, sy = 0.f;
        #pragma unroll
        for (int m = 0; m < 3; m++) {
            float2 x = *(const float2*)&xvT[m * 1024 + u * 32 + n2];
            float2 a = *(const float2*)&avT[m * 1024 + v * 32 + n2];
            sx = fmaf(x.x, a.x, sx); sy = fmaf(x.y, a.y, sy);
        }
        r.x = INV_SQRT3 * sx; r.y = INV_SQRT3 * sy;
    }
    return r;
}

__device__ __forceinline__ void build2_6(const float* xsT, const float* asT,
                                         const float* xvT, const float* avT,
                                         int k, int r0, float* o) {
    if (k < 2048) {
        int u = k >> 5, v = k & 31;
        #pragma unroll
        for (int j = 0; j < 6; j++) {
            int r = r0 + j, m = r >> 5, n = r & 31;
            o[j] = xsT[u * 32 + n] * avT[m * 1024 + v * 32 + n];
        }
    } else {
        int k2 = k - 2048, u = k2 / 96, v = k2 - u * 96;
        #pragma unroll
        for (int j = 0; j < 6; j++) {
            int r = r0 + j, m = r >> 5, n = r & 31;
            o[j] = xvT[m * 1024 + u * 32 + n] * asT[v * 32 + n];
        }
    }
}

__global__ void __launch_bounds__(128, 4) node_kernel(
    const float* __restrict__ nf,
    const float* __restrict__ Wss, const float* __restrict__ Wvv,
    const float* __restrict__ Wsv, const float* __restrict__ Wvs)
{
    extern __shared__ float sm[];
    float* s_xsT = sm;
    float* s_xvT = sm + 2048;
    float* s_asT = sm + 5120;
    float* s_avT = sm + 8192;
    float* sCh   = sm + 11264;   // 2 x 1024

    const int t     = threadIdx.x;
    const int tile  = blockIdx.x >> 3;
    const int slice = blockIdx.x & 7;
    const int n0    = tile * 32;

    for (int i = t; i < 32 * 160; i += 128) {
        int n = i / 160, c = i - n * 160;
        int gn = n0 + n;
        float v = (gn < N_NODES) ? nf[(size_t)gn * 160 + c] : 0.f;
        if (c < 64) s_xsT[c * 32 + n] = v;
        else { int c2 = c - 64, u = c2 / 3, m = c2 - u * 3;
               s_xvT[m * 1024 + u * 32 + n] = v; }
    }
    for (int i = t; i < 32 * 192; i += 128) {
        int n = i / 192, c = i - n * 192;
        int gn = n0 + n;
        float v = (gn < N_NODES) ? g_agg[(size_t)gn * 192 + c] : 0.f;
        if (c < 96) s_asT[c * 32 + n] = v;
        else { int c2 = c - 96, w = c2 / 3, m = c2 - w * 3;
               s_avT[m * 1024 + w * 32 + n] = v; }
    }
    __syncthreads();

    const int kb  = t >> 4;          // chunk k-row (8)
    const int n2b = (t & 15) * 2;    // stage1 A staging: 2 nodes
    const int wB6 = (t & 15) * 6;    // stage1 B staging: 6 w
    const int r6b = (t & 15) * 6;    // stage2 A staging: 6 rows
    const int w2B = (t & 15) * 2;    // stage2 B staging: 2 w

    // ---------------- stage 1: us partial, 112 chunks of 8 ----------------
    {
        const int k_off = slice * 896;   // 7168 / 8
        const int ng = (t & 7) * 4;
        const int w6 = (t >> 3) * 6;
        float acc[24];
        #pragma unroll
        for (int i = 0; i < 24; i++) acc[i] = 0.f;

        {   // prologue (generic region select: slice may start in vv region)
            int kw = k_off + kb;
            float2 a0 = build1_2(s_xsT, s_asT, s_xvT, s_avT, kw, n2b);
            *(float2*)&sCh[kb * 32 + n2b] = a0;
            const float* src = (kw < 6144) ? Wss + (size_t)kw * 96 + wB6
                                           : Wvv + (size_t)(kw - 6144) * 96 + wB6;
            *(float2*)&sCh[256 + kb * 96 + wB6    ] = *(const float2*)(src);
            *(float2*)&sCh[256 + kb * 96 + wB6 + 2] = *(const float2*)(src + 2);
            *(float2*)&sCh[256 + kb * 96 + wB6 + 4] = *(const float2*)(src + 4);
        }
        __syncthreads();

        int cur = 0;
        for (int c = 0; c < 112; c++) {
            float2 an, bn0, bn1, bn2;
            const bool pre = (c + 1 < 112);
            if (pre) {
                int kw = k_off + (c + 1) * 8 + kb;
                const float* src = (kw < 6144) ? Wss + (size_t)kw * 96 + wB6
                                               : Wvv + (size_t)(kw - 6144) * 96 + wB6;
                bn0 = *(const float2*)(src);
                bn1 = *(const float2*)(src + 2);
                bn2 = *(const float2*)(src + 4);
                an = build1_2(s_xsT, s_asT, s_xvT, s_avT, kw, n2b);
            }
            const float* A = sCh + cur * 1024;
            const float* B = A + 256;
            #pragma unroll
            for (int kk = 0; kk < 8; kk++) {
                float4 a  = *(const float4*)&A[kk * 32 + ng];
                float2 b0 = *(const float2*)&B[kk * 96 + w6];
                float2 b1 = *(const float2*)&B[kk * 96 + w6 + 2];
                float2 b2 = *(const float2*)&B[kk * 96 + w6 + 4];
                acc[0]  = fmaf(a.x, b0.x, acc[0]);
                acc[1]  = fmaf(a.x, b0.y, acc[1]);
                acc[2]  = fmaf(a.x, b1.x, acc[2]);
                acc[3]  = fmaf(a.x, b1.y, acc[3]);
                acc[4]  = fmaf(a.x, b2.x, acc[4]);
                acc[5]  = fmaf(a.x, b2.y, acc[5]);
                acc[6]  = fmaf(a.y, b0.x, acc[6]);
                acc[7]  = fmaf(a.y, b0.y, acc[7]);
                acc[8]  = fmaf(a.y, b1.x, acc[8]);
                acc[9]  = fmaf(a.y, b1.y, acc[9]);
                acc[10] = fmaf(a.y, b2.x, acc[10]);
                acc[11] = fmaf(a.y, b2.y, acc[11]);
                acc[12] = fmaf(a.z, b0.x, acc[12]);
                acc[13] = fmaf(a.z, b0.y, acc[13]);
                acc[14] = fmaf(a.z, b1.x, acc[14]);
                acc[15] = fmaf(a.z, b1.y, acc[15]);
                acc[16] = fmaf(a.z, b2.x, acc[16]);
                acc[17] = fmaf(a.z, b2.y, acc[17]);
                acc[18] = fmaf(a.w, b0.x, acc[18]);
                acc[19] = fmaf(a.w, b0.y, acc[19]);
                acc[20] = fmaf(a.w, b1.x, acc[20]);
                acc[21] = fmaf(a.w, b1.y, acc[21]);
                acc[22] = fmaf(a.w, b2.x, acc[22]);
                acc[23] = fmaf(a.w, b2.y, acc[23]);
            }
            if (pre) {
                float* An = sCh + (cur ^ 1) * 1024;
                float* Bn = An + 256;
                *(float2*)&An[kb * 32 + n2b] = an;
                *(float2*)&Bn[kb * 96 + wB6    ] = bn0;
                *(float2*)&Bn[kb * 96 + wB6 + 2] = bn1;
                *(float2*)&Bn[kb * 96 + wB6 + 4] = bn2;
            }
            __syncthreads();
            cur ^= 1;
        }
        #pragma unroll
        for (int i = 0; i < 4; i++) {
            int gn = n0 + ng + i;
            if (gn < N_NODES) {
                #pragma unroll
                for (int j = 0; j < 6; j++)
                    atomicAdd(&g_upd[(size_t)gn * 192 + w6 + j], acc[i * 6 + j]);
            }
        }
    }
    __syncthreads();

    // ---------------- stage 2: uv partial, 80 chunks of 8 ----------------
    {
        const int k_off = slice * 640;   // 5120 / 8
        const int w4 = (t & 7) * 4;
        const int r6 = (t >> 3) * 6;
        float acc[24];
        #pragma unroll
        for (int i = 0; i < 24; i++) acc[i] = 0.f;

        {   // prologue (generic region select: slice may start in vs region)
            int kw = k_off + kb;
            float o[6];
            build2_6(s_xsT, s_asT, s_xvT, s_avT, kw, r6b, o);
            *(float2*)&sCh[kb * 96 + r6b    ] = *(float2*)&o[0];
            *(float2*)&sCh[kb * 96 + r6b + 2] = *(float2*)&o[2];
            *(float2*)&sCh[kb * 96 + r6b + 4] = *(float2*)&o[4];
            const float* src = (kw < 2048) ? Wsv + (size_t)kw * 32 + w2B
                                           : Wvs + (size_t)(kw - 2048) * 32 + w2B;
            *(float2*)&sCh[768 + kb * 32 + w2B] = *(const float2*)src;
        }
        __syncthreads();

        int cur = 0;
        for (int c = 0; c < 80; c++) {
            float on[6];
            float2 bn;
            const bool pre = (c + 1 < 80);
            if (pre) {
                int kw = k_off + (c + 1) * 8 + kb;
                const float* src = (kw < 2048) ? Wsv + (size_t)kw * 32 + w2B
                                               : Wvs + (size_t)(kw - 2048) * 32 + w2B;
                bn = *(const float2*)src;
                build2_6(s_xsT, s_asT, s_xvT, s_avT, kw, r6b, on);
            }
            const float* A = sCh + cur * 1024;
            const float* B = A + 768;
            #pragma unroll
            for (int kk = 0; kk < 8; kk++) {
                float2 a01 = *(const float2*)&A[kk * 96 + r6];
                float2 a23 = *(const float2*)&A[kk * 96 + r6 + 2];
                float2 a45 = *(const float2*)&A[kk * 96 + r6 + 4];
                float4 b   = *(const float4*)&B[kk * 32 + w4];
                acc[0]  = fmaf(a01.x, b.x, acc[0]);
                acc[1]  = fmaf(a01.x, b.y, acc[1]);
                acc[2]  = fmaf(a01.x, b.z, acc[2]);
                acc[3]  = fmaf(a01.x, b.w, acc[3]);
                acc[4]  = fmaf(a01.y, b.x, acc[4]);
                acc[5]  = fmaf(a01.y, b.y, acc[5]);
                acc[6]  = fmaf(a01.y, b.z, acc[6]);
                acc[7]  = fmaf(a01.y, b.w, acc[7]);
                acc[8]  = fmaf(a23.x, b.x, acc[8]);
                acc[9]  = fmaf(a23.x, b.y, acc[9]);
                acc[10] = fmaf(a23.x, b.z, acc[10]);
                acc[11] = fmaf(a23.x, b.w, acc[11]);
                acc[12] = fmaf(a23.y, b.x, acc[12]);
                acc[13] = fmaf(a23.y, b.y, acc[13]);
                acc[14] = fmaf(a23.y, b.z, acc[14]);
                acc[15] = fmaf(a23.y, b.w, acc[15]);
                acc[16] = fmaf(a45.x, b.x, acc[16]);
                acc[17] = fmaf(a45.x, b.y, acc[17]);
                acc[18] = fmaf(a45.x, b.z, acc[18]);
                acc[19] = fmaf(a45.x, b.w, acc[19]);
                acc[20] = fmaf(a45.y, b.x, acc[20]);
                acc[21] = fmaf(a45.y, b.y, acc[21]);
                acc[22] = fmaf(a45.y, b.z, acc[22]);
                acc[23] = fmaf(a45.y, b.w, acc[23]);
            }
            if (pre) {
                float* An = sCh + (cur ^ 1) * 1024;
                float* Bn = An + 768;
                *(float2*)&An[kb * 96 + r6b    ] = *(float2*)&on[0];
                *(float2*)&An[kb * 96 + r6b + 2] = *(float2*)&on[2];
                *(float2*)&An[kb * 96 + r6b + 4] = *(float2*)&on[4];
                *(float2*)&Bn[kb * 32 + w2B] = bn;
            }
            __syncthreads();
            cur ^= 1;
        }
        #pragma unroll
        for (int i = 0; i < 6; i++) {
            int r = r6 + i, m = r >> 5, n = r & 31;
            int gn = n0 + n;
            if (gn < N_NODES) {
                #pragma unroll
                for (int j = 0; j < 4; j++)
                    atomicAdd(&g_upd[(size_t)gn * 192 + 96 + (w4 + j) * 3 + m],
                              acc[i * 4 + j]);
            }
        }
    }
}

// ============================================================================
// EPILOGUE: norm + gate + linear + residual.  (unchanged)
// ============================================================================
__global__ void __launch_bounds__(128) epilogue_kernel(
    const float* __restrict__ nf,
    const float* __restrict__ WLs, const float* __restrict__ WLv,
    float* __restrict__ out)
{
    __shared__ float s_WLs[4096];
    __shared__ float s_WLv[1024];
    __shared__ float s_us[3072];
    __shared__ float s_uv[3072];

    const int t  = threadIdx.x;
    const int n0 = blockIdx.x * 32;

    for (int i = t; i < 4096; i += 128) s_WLs[i] = WLs[i];
    for (int i = t; i < 1024; i += 128) s_WLv[i] = WLv[i];
    for (int i = t; i < 3072; i += 128) {
        int n = i / 96, c = i - n * 96;
        int gn = n0 + n;
        float us = 0.f, uv = 0.f;
        if (gn < N_NODES) {
            us = g_upd[(size_t)gn * 192 + c];
            uv = g_upd[(size_t)gn * 192 + 96 + c];
        }
        s_us[i] = us; s_uv[i] = uv;
    }
    __syncthreads();

    for (int i = t; i < 2048; i += 128) {
        int n = i >> 6, u = i & 63;
        float x = s_us[n * 96 + u] * NORM_UPD_S;
        s_us[n * 96 + u] = x / (1.f + expf(-x));
    }
    for (int i = t; i < 1024; i += 128) {
        int n = i >> 5, w = i & 31;
        float x = s_us[n * 96 + 64 + w] * NORM_UPD_S;
        s_us[n * 96 + 64 + w] = 1.f / (1.f + expf(-x));
    }
    __syncthreads();
    for (int i = t; i < 3072; i += 128) {
        int n = i / 96, c = i - n * 96;
        int u = c / 3;
        s_uv[i] = s_uv[i] * NORM_UPD_V * s_us[n * 96 + 64 + u];
    }
    __syncthreads();

    for (int i = t; i < 2048; i += 128) {
        int n = i >> 6, w = i & 63;
        int gn = n0 + n;
        if (gn < N_NODES) {
            float s = 0.f;
            #pragma unroll 8
            for (int u = 0; u < 64; u++)
                s = fmaf(s_us[n * 96 + u], s_WLs[u * 64 + w], s);
            out[(size_t)gn * 160 + w] = nf[(size_t)gn * 160 + w] + s * NORM_LIN64;
        }
    }
    for (int i = t; i < 3072; i += 128) {
        int n = i / 96, c = i - n * 96;
        int w = c / 3, m = c - w * 3;
        int gn = n0 + n;
        if (gn < N_NODES) {
            float s = 0.f;
            #pragma unroll
            for (int u = 0; u < 32; u++)
                s = fmaf(s_uv[n * 96 + u * 3 + m], s_WLv[u * 32 + w], s);
            out[(size_t)gn * 160 + 64 + c] = nf[(size_t)gn * 160 + 64 + c] + s * NORM_LIN32;
        }
    }
}

extern "C" void kernel_launch(void* const* d_in, const int* in_sizes, int n_in,
                              void* d_out, int out_size) {
    const float* nf   = (const float*)d_in[0];
    const float* ea   = (const float*)d_in[1];
    const float* Wmss = (const float*)d_in[2];
    const float* Wmvv = (const float*)d_in[3];
    const float* Wmsv = (const float*)d_in[4];
    const float* Wmvs = (const float*)d_in[5];
    const float* WLms = (const float*)d_in[6];
    const float* WLmv = (const float*)d_in[7];
    const float* Wuss = (const float*)d_in[8];
    const float* Wuvv = (const float*)d_in[9];
    const float* Wusv = (const float*)d_in[10];
    const float* Wuvs = (const float*)d_in[11];
    const float* WLus = (const float*)d_in[12];
    const float* WLuv = (const float*)d_in[13];
    const int*   eidx = (const int*)d_in[14];
    float* out = (float*)d_out;

    cudaFuncSetAttribute(node_kernel, cudaFuncAttributeMaxDynamicSharedMemorySize,
                         NODE_SMEM_BYTES);
    cudaFuncSetAttribute(node_kernel, cudaFuncAttributePreferredSharedMemoryCarveout,
                         100);

    zero_kernel<<<(N_NODES * 192 + 255) / 256, 256>>>();
    precompute_z<<<(N_NODES + 31) / 32, 256>>>(nf, Wmss, Wmvv, Wmsv, Wmvs);
    edge_kernel<<<N_EDGES / EB, 256>>>(ea, WLms, WLmv, eidx);
    node_kernel<<<KSPLIT * ((N_NODES + 31) / 32), 128, NODE_SMEM_BYTES>>>(
        nf, Wuss, Wuvv, Wusv, Wuvs);
    epilogue_kernel<<<(N_NODES + 31) / 32, 128>>>(nf, WLus, WLuv, out);
}